// round 16
// baseline (speedup 1.0000x reference)
#include <cuda_runtime.h>
#include <math.h>
#include <stdint.h>

// Problem dims (fixed)
#define B_  64
#define T_  512
#define D_  256
#define H_  256
#define G4  1024          // 4*H
#define NBG 16            // batch groups (4 batches each)
#define NSL 8             // hidden-slice blocks per group (32 units each)
#define NB_SCAN (NBG*NSL) // 128 blocks
#define SENT 0x7FBFFFFFu  // NaN sentinel (unreachable: gemm sums & sigm*tanh are finite)

typedef unsigned long long u64;
typedef unsigned int u32;

// ---------------- device scratch ----------------
__device__ float g_Wc[G4 * D_];                 // combined weight W_ih @ W_att
__device__ float g_bc[G4];                      // combined bias
__device__ float g_vlin0[B_ * D_];              // vlin[:,0]
__device__ float g_a[B_ * T_];                  // attention scalars a[b,t]
__device__ float g_gates[(size_t)T_ * B_ * G4]; // input gates [t][b][grow]  (sentinel-tagged)
__device__ float g_hT[(size_t)T_ * NBG * NSL * 128]; // per-step h fragments [t][g][s][jl][b]

#define N_HT_U4  ((size_t)T_ * NBG * NSL * 128 / 4)       // 2097152
#define N_GT_U4  ((size_t)T_ * B_ * G4 / 4)               // 8388608
#define N_POISON_U4 (N_HT_U4 + N_GT_U4)                   // 10485760

// ---------------- helpers ----------------
__device__ __forceinline__ float sigm(float x) {
    return __fdividef(1.0f, 1.0f + __expf(-x));
}
__device__ __forceinline__ float tanh_fast(float x) {
    return fmaf(2.0f, __fdividef(1.0f, 1.0f + __expf(-2.0f * x)), -1.0f);
}
__device__ __forceinline__ u64 pack2(float x, float y) {
    u64 r;
    asm("mov.b64 %0, {%1, %2};" : "=l"(r) : "f"(x), "f"(y));
    return r;
}
__device__ __forceinline__ u64 fma2(u64 a, u64 b, u64 c) {
    u64 d;
    asm("fma.rn.f32x2 %0, %1, %2, %3;" : "=l"(d) : "l"(a), "l"(b), "l"(c));
    return d;
}
__device__ __forceinline__ float2 unpack2(u64 v) {
    float2 f;
    asm("mov.b64 {%0, %1}, %2;" : "=f"(f.x), "=f"(f.y) : "l"(v));
    return f;
}
__device__ __forceinline__ uint4 ld_vol4(const float* p) {
    uint4 v;
    asm volatile("ld.volatile.global.v4.u32 {%0,%1,%2,%3}, [%4];"
                 : "=r"(v.x), "=r"(v.y), "=r"(v.z), "=r"(v.w) : "l"(p));
    return v;
}
__device__ __forceinline__ u32 ld_vol_u32(const u32* p) {
    u32 v;
    asm volatile("ld.volatile.global.u32 %0, [%1];" : "=r"(v) : "l"(p));
    return v;
}
__device__ __forceinline__ void st_vol(float* p, float v) {
    asm volatile("st.volatile.global.f32 [%0], %1;" :: "l"(p), "f"(v) : "memory");
}

// ---------------- kernel: poison h + gates buffers with sentinel ----------------
__global__ void k_poison() {
    size_t i = (size_t)blockIdx.x * blockDim.x + threadIdx.x;
    uint4 sv = make_uint4(SENT, SENT, SENT, SENT);
    if (i < N_HT_U4) ((uint4*)g_hT)[i] = sv;
    else if (i < N_POISON_U4) ((uint4*)g_gates)[i - N_HT_U4] = sv;
}

// ---------------- kernel: Wc = W_ih @ W_att  AND  bc = W_ih@b_att + b_ih + b_hh ----
__global__ void k_wcbc(const float* __restrict__ W_ih, const float* __restrict__ W_att,
                       const float* __restrict__ b_att, const float* __restrict__ b_ih,
                       const float* __restrict__ b_hh) {
    int g = blockIdx.x;
    int k = threadIdx.x;
    __shared__ float wrow[D_];
    __shared__ float red[8];
    float w = W_ih[g * D_ + k];
    wrow[k] = w;
    __syncthreads();
    // bc reduction (reuses staged row)
    float pv = w * b_att[k];
#pragma unroll
    for (int off = 16; off; off >>= 1) pv += __shfl_down_sync(0xffffffffu, pv, off);
    if ((k & 31) == 0) red[k >> 5] = pv;
    float acc = 0.f;
#pragma unroll 8
    for (int d = 0; d < D_; d++) acc += wrow[d] * W_att[d * D_ + k];
    g_Wc[g * D_ + k] = acc;
    __syncthreads();
    if (k == 0) {
        float s = 0.f;
#pragma unroll
        for (int i = 0; i < 8; i++) s += red[i];
        g_bc[g] = s + b_ih[g] + b_hh[g];
    }
}

// ---------------- kernel: vlin0[b,:] = values[b,0,:] @ W_att^T + b_att ----------------
// grid (B_, 4): warp handles 8 rows (coalesced W_att reads), shuffle reduce.
__global__ void k_vlin0(const float* __restrict__ values, const float* __restrict__ W_att,
                        const float* __restrict__ b_att) {
    int b = blockIdx.x;
    int wrp = threadIdx.x >> 5;
    int lane = threadIdx.x & 31;
    __shared__ float v[D_];
    v[threadIdx.x] = values[(size_t)b * T_ * D_ + threadIdx.x];
    __syncthreads();
    for (int i = 0; i < 8; i++) {
        int d = blockIdx.y * 64 + wrp * 8 + i;
        const float* wr = W_att + (size_t)d * D_;
        float acc = 0.f;
#pragma unroll
        for (int k = lane; k < D_; k += 32) acc += v[k] * wr[k];
#pragma unroll
        for (int off = 16; off; off >>= 1) acc += __shfl_down_sync(0xffffffffu, acc, off);
        if (lane == 0) g_vlin0[b * D_ + d] = acc + b_att[d];
    }
}

// ---------------- kernel: a[b,t] = sigmoid(vlin0[b] . values[b,t]) ----------------
__global__ void k_a(const float* __restrict__ values) {
    int w = (blockIdx.x * blockDim.x + threadIdx.x) >> 5;
    int lane = threadIdx.x & 31;
    int b = w >> 9, t = w & (T_ - 1);
    const float* vp = values + ((size_t)b * T_ + t) * D_;
    const float* lp = g_vlin0 + b * D_;
    float acc = 0.f;
#pragma unroll
    for (int k = lane; k < D_; k += 32) acc += vp[k] * lp[k];
#pragma unroll
    for (int off = 16; off; off >>= 1) acc += __shfl_down_sync(0xffffffffu, acc, off);
    if (lane == 0) g_a[w] = 1.0f / (1.0f + expf(-acc));
}

// ---------------- big GEMM: gates[t][b][g] = values[b,t,:].Wc[g,:] + bc[g] ----------
// Tile: (64 batch x 2 t) rows x 128 n per block, 256 threads, 8x8 microtile (FFMA2).
// grid = dim3(8, 256): n-blocks on the FAST axis, t-pairs on the SLOW axis, so the
// 8 n-tiles of each t complete together and gates arrive in INCREASING-t order —
// required for the overlapped scan to consume them as they are produced.
// Launched with ~100KB UNUSED dynamic smem: caps occupancy at 1 block/SM so every
// SM keeps room for a co-resident k_scan block (true overlap via gates sentinel).
#define PA 132   // smem row pitch (floats), float4-aligned
__global__ __launch_bounds__(256) void k_gemm(const float* __restrict__ values) {
    int n0 = blockIdx.x * 128;      // FAST axis: n-tile
    int t0 = blockIdx.y * 2;        // SLOW axis: t-pair -> t-major completion order

    __shared__ float As[16 * PA];   // [k][r]  r = tt*64 + b
    __shared__ float Bs[16 * PA];   // [k][n]

    int tid = threadIdx.x;
    int tx = tid & 15;              // row quad group
    int ty = tid >> 4;              // n quad group

    const float* gp;
    float* scol;
    {
        int r = tid & 127;
        if (tid < 128) {
            int b = r & 63, tt = r >> 6;
            gp = values + ((size_t)b * T_ + t0 + tt) * D_;
            scol = As + r;
        } else {
            gp = g_Wc + (size_t)(n0 + r) * D_;
            scol = Bs + r;
        }
    }

    float4 pf0 = ((const float4*)gp)[0];
    float4 pf1 = ((const float4*)gp)[1];
    float4 pf2 = ((const float4*)gp)[2];
    float4 pf3 = ((const float4*)gp)[3];

    u64 acc[2][4][4];
#pragma unroll
    for (int a = 0; a < 2; a++)
#pragma unroll
        for (int i = 0; i < 4; i++)
#pragma unroll
            for (int j = 0; j < 4; j++) acc[a][i][j] = 0ull;

    for (int c = 0; c < 16; c++) {
        __syncthreads();
        scol[ 0 * PA] = pf0.x; scol[ 1 * PA] = pf0.y; scol[ 2 * PA] = pf0.z; scol[ 3 * PA] = pf0.w;
        scol[ 4 * PA] = pf1.x; scol[ 5 * PA] = pf1.y; scol[ 6 * PA] = pf1.z; scol[ 7 * PA] = pf1.w;
        scol[ 8 * PA] = pf2.x; scol[ 9 * PA] = pf2.y; scol[10 * PA] = pf2.z; scol[11 * PA] = pf2.w;
        scol[12 * PA] = pf3.x; scol[13 * PA] = pf3.y; scol[14 * PA] = pf3.z; scol[15 * PA] = pf3.w;
        __syncthreads();

        if (c < 15) {
            const float* np = gp + (c + 1) * 16;
            pf0 = ((const float4*)np)[0];
            pf1 = ((const float4*)np)[1];
            pf2 = ((const float4*)np)[2];
            pf3 = ((const float4*)np)[3];
        }

#pragma unroll
        for (int k = 0; k < 16; k++) {
            float4 a0 = *(const float4*)&As[k * PA + 4 * tx];
            float4 a1 = *(const float4*)&As[k * PA + 64 + 4 * tx];
            float4 bv0 = *(const float4*)&Bs[k * PA + 4 * ty];
            float4 bv1 = *(const float4*)&Bs[k * PA + 64 + 4 * ty];
            u64 b00 = *(u64*)&bv0.x;
            u64 b01 = *(u64*)&bv0.z;
            u64 b10 = *(u64*)&bv1.x;
            u64 b11 = *(u64*)&bv1.z;

            u64 p;
            p = pack2(a0.x, a0.x);
            acc[0][0][0] = fma2(p, b00, acc[0][0][0]); acc[0][0][1] = fma2(p, b01, acc[0][0][1]);
            acc[0][0][2] = fma2(p, b10, acc[0][0][2]); acc[0][0][3] = fma2(p, b11, acc[0][0][3]);
            p = pack2(a0.y, a0.y);
            acc[0][1][0] = fma2(p, b00, acc[0][1][0]); acc[0][1][1] = fma2(p, b01, acc[0][1][1]);
            acc[0][1][2] = fma2(p, b10, acc[0][1][2]); acc[0][1][3] = fma2(p, b11, acc[0][1][3]);
            p = pack2(a0.z, a0.z);
            acc[0][2][0] = fma2(p, b00, acc[0][2][0]); acc[0][2][1] = fma2(p, b01, acc[0][2][1]);
            acc[0][2][2] = fma2(p, b10, acc[0][2][2]); acc[0][2][3] = fma2(p, b11, acc[0][2][3]);
            p = pack2(a0.w, a0.w);
            acc[0][3][0] = fma2(p, b00, acc[0][3][0]); acc[0][3][1] = fma2(p, b01, acc[0][3][1]);
            acc[0][3][2] = fma2(p, b10, acc[0][3][2]); acc[0][3][3] = fma2(p, b11, acc[0][3][3]);
            p = pack2(a1.x, a1.x);
            acc[1][0][0] = fma2(p, b00, acc[1][0][0]); acc[1][0][1] = fma2(p, b01, acc[1][0][1]);
            acc[1][0][2] = fma2(p, b10, acc[1][0][2]); acc[1][0][3] = fma2(p, b11, acc[1][0][3]);
            p = pack2(a1.y, a1.y);
            acc[1][1][0] = fma2(p, b00, acc[1][1][0]); acc[1][1][1] = fma2(p, b01, acc[1][1][1]);
            acc[1][1][2] = fma2(p, b10, acc[1][1][2]); acc[1][1][3] = fma2(p, b11, acc[1][1][3]);
            p = pack2(a1.z, a1.z);
            acc[1][2][0] = fma2(p, b00, acc[1][2][0]); acc[1][2][1] = fma2(p, b01, acc[1][2][1]);
            acc[1][2][2] = fma2(p, b10, acc[1][2][2]); acc[1][2][3] = fma2(p, b11, acc[1][2][3]);
            p = pack2(a1.w, a1.w);
            acc[1][3][0] = fma2(p, b00, acc[1][3][0]); acc[1][3][1] = fma2(p, b01, acc[1][3][1]);
            acc[1][3][2] = fma2(p, b10, acc[1][3][2]); acc[1][3][3] = fma2(p, b11, acc[1][3][3]);
        }
    }

    float4 biasA = *(const float4*)&g_bc[n0 + 4 * ty];
    float4 biasB = *(const float4*)&g_bc[n0 + 64 + 4 * ty];
#pragma unroll
    for (int tt = 0; tt < 2; tt++) {
#pragma unroll
        for (int i = 0; i < 4; i++) {
            int b = 4 * tx + i;
            float* op = g_gates + ((size_t)(t0 + tt) * B_ + b) * G4 + n0;
            float2 p0 = unpack2(acc[tt][i][0]);
            float2 p1 = unpack2(acc[tt][i][1]);
            float2 p2 = unpack2(acc[tt][i][2]);
            float2 p3 = unpack2(acc[tt][i][3]);
            *(float4*)&op[4 * ty] =
                make_float4(p0.x + biasA.x, p0.y + biasA.y, p1.x + biasA.z, p1.y + biasA.w);
            *(float4*)&op[64 + 4 * ty] =
                make_float4(p2.x + biasB.x, p2.y + biasB.y, p3.x + biasB.z, p3.y + biasB.w);
        }
    }
}

// ---------------- persistent scan kernel (L2 data-as-tag, gemm-overlapped) --------
// 128 blocks = 16 groups x 8 slices. Block (g,s): batches 4g..4g+3, units 32s..32s+31.
// W rows 4rq,4rq+1 in REGISTERS; rows 4rq+2,4rq+3 in thread-private SMEM (register
// relief: __launch_bounds__(256,2) guarantees <=128 regs so a gemm block co-resides).
// h exchange: per-step sentinel buffers in L2 (proven R12). gates ALSO sentinel-
// polled -> gemm runs concurrently (t-major production order). alpha in-loop.
__global__ __launch_bounds__(256, 2) void k_scan(const float* __restrict__ Whh,
                                                 const float* __restrict__ Deltas,
                                                 float* __restrict__ out) {
    extern __shared__ float sm[];
    float* h_s2 = sm;                          // 8*256 floats (8KB) [ks][dup-pair frags]
    float* wBs  = sm + 8 * 256;                // 16384 floats (64KB) [m][ks][rq] float4
    u64* psumU  = (u64*)(sm + 8 * 256 + 16384);// 2 * 32*65 u64 (33.3KB), parity-buffered

    int tid = threadIdx.x;
    int bid = blockIdx.x;
    int g = bid >> 3, s = bid & 7;

    int ks = tid >> 5;            // warp id == peer slice consumed
    int rq = tid & 31;            // row quad (rows 4rq..4rq+3)

    // ---- W slice: rows 4rq,4rq+1 -> regs; rows 4rq+2,4rq+3 -> private smem ----
    u64 wA[32];
    {
        int r0 = 4 * rq;
        int q = r0 >> 5;
        int jb = r0 & 31;
        const float* wb = Whh + (size_t)(q * 256 + s * 32 + jb) * 256 + 32 * ks;
#pragma unroll
        for (int kc = 0; kc < 32; kc++) wA[kc] = pack2(wb[kc], wb[256 + kc]);
        float4* w4 = (float4*)wBs;
#pragma unroll
        for (int m = 0; m < 16; m++) {
            u64 b0 = pack2(wb[512 + 2 * m],     wb[768 + 2 * m]);
            u64 b1 = pack2(wb[512 + 2 * m + 1], wb[768 + 2 * m + 1]);
            float4 q4;
            *(u64*)&q4.x = b0;
            *(u64*)&q4.z = b1;
            w4[(m * 8 + ks) * 32 + rq] = q4;   // written & read by this thread only
        }
    }

    // update identity (tid < 128)
    int ub = tid >> 5;            // 0..3 batch-local
    int jl = tid & 31;
    int bg = g * 4 + ub;          // global batch
    int jglob = s * 32 + jl;      // global hidden unit

    float c_reg = 0.f, c0_reg = 0.f, dacc = 0.f;

    // ---- prologue t = 0 (h=0, c=0; carry c stays zero — faithful quirk) ----
    if (tid < 128) {
        const u32* g0 = (const u32*)(g_gates + (size_t)bg * G4);
        u32 uzi, uzg, uzo;
        do {
            uzi = ld_vol_u32(g0 + jglob);
            uzg = ld_vol_u32(g0 + 512 + jglob);
            uzo = ld_vol_u32(g0 + 768 + jglob);
        } while (uzi == SENT || uzg == SENT || uzo == SENT);
        float zi = __uint_as_float(uzi);
        float zg = __uint_as_float(uzg);
        float zo = __uint_as_float(uzo);
        c0_reg = sigm(zi) * tanh_fast(zg);
        float h1 = sigm(zo) * tanh_fast(c0_reg);
        dacc = Deltas[(size_t)bg * T_ * D_ + jglob];   // cumsum through t=0
        st_vol(g_hT + (((size_t)0 * NBG + g) * NSL + s) * 128 + jl * 4 + ub, h1);
        out[(size_t)bg * (T_ * H_) + jglob] = h1;
    }

    for (int t = 1; t < T_; t++) {
        // early volatile prefetch of gates/Deltas/a (sentinel re-check after barrier)
        u32 ug0 = SENT, ug1 = SENT, ug2 = SENT, ug3 = SENT;
        float dlt = 0.f, av = 0.f;
        const u32* gt = (const u32*)(g_gates + ((size_t)t * B_ + bg) * G4);
        if (tid < 128) {
            ug0 = ld_vol_u32(gt + jglob);
            ug1 = ld_vol_u32(gt + 256 + jglob);
            ug2 = ld_vol_u32(gt + 512 + jglob);
            ug3 = ld_vol_u32(gt + 768 + jglob);
            dlt = Deltas[((size_t)bg * T_ + t) * D_ + jglob];
            av  = g_a[bg * T_ + t];
        }

        // poll peer h fragment: data IS the tag (proven R12 protocol)
        {
            const float* fp = g_hT + (((size_t)(t - 1) * NBG + g) * NSL + ks) * 128 + rq * 4;
            uint4 u;
            do {
                u = ld_vol4(fp);
            } while (u.x == SENT || u.y == SENT || u.z == SENT || u.w == SENT);
            float2* d = (float2*)(h_s2 + ks * 256);
            float hx = __uint_as_float(u.x);
            float hy = __uint_as_float(u.y);
            float hz = __uint_as_float(u.z);
            float hw = __uint_as_float(u.w);
            d[0 * 32 + rq] = make_float2(hx, hx);
            d[1 * 32 + rq] = make_float2(hy, hy);
            d[2 * 32 + rq] = make_float2(hz, hz);
            d[3 * 32 + rq] = make_float2(hw, hw);
        }
        __syncwarp();

        // dot: wA in regs, wB via private LDS.128, h via broadcast LDS.128, FFMA2
        {
            const float* hp = h_s2 + ks * 256;
            const float4* wbp = (const float4*)wBs + ks * 32 + rq;
            u64 a00 = 0, a01 = 0, a02 = 0, a03 = 0;
            u64 a10 = 0, a11 = 0, a12 = 0, a13 = 0;
#pragma unroll
            for (int m = 0; m < 16; m++) {
                float4 q0 = *(const float4*)(hp + 4 * m);
                float4 q1 = *(const float4*)(hp + 64 + 4 * m);
                float4 q2 = *(const float4*)(hp + 128 + 4 * m);
                float4 q3 = *(const float4*)(hp + 192 + 4 * m);
                float4 wq = wbp[m * 256];
                u64 wa0 = wA[2 * m], wa1 = wA[2 * m + 1];
                u64 wb0 = *(u64*)&wq.x, wb1 = *(u64*)&wq.z;
                u64 h00 = *(u64*)&q0.x, h01 = *(u64*)&q0.z;
                u64 h10 = *(u64*)&q1.x, h11 = *(u64*)&q1.z;
                u64 h20 = *(u64*)&q2.x, h21 = *(u64*)&q2.z;
                u64 h30 = *(u64*)&q3.x, h31 = *(u64*)&q3.z;
                a00 = fma2(wa0, h00, a00); a00 = fma2(wa1, h01, a00);
                a01 = fma2(wa0, h10, a01); a01 = fma2(wa1, h11, a01);
                a02 = fma2(wa0, h20, a02); a02 = fma2(wa1, h21, a02);
                a03 = fma2(wa0, h30, a03); a03 = fma2(wa1, h31, a03);
                a10 = fma2(wb0, h00, a10); a10 = fma2(wb1, h01, a10);
                a11 = fma2(wb0, h10, a11); a11 = fma2(wb1, h11, a11);
                a12 = fma2(wb0, h20, a12); a12 = fma2(wb1, h21, a12);
                a13 = fma2(wb0, h30, a13); a13 = fma2(wb1, h31, a13);
            }
            u64* pb = psumU + (t & 1) * (32 * 65) + rq * 65 + ks * 4;
            pb[0] = a00; pb[1] = a01; pb[2] = a02; pb[3] = a03;
            pb[32 + 0] = a10; pb[32 + 1] = a11; pb[32 + 2] = a12; pb[32 + 3] = a13;
        }
        __syncthreads();   // psum[t&1] ready (single barrier per step; parity-buffered)

        // cell update: 128 threads, one per (batch, unit)
        if (tid < 128) {
            // finish gates poll (normally already satisfied by the prefetch)
            while (ug0 == SENT || ug1 == SENT || ug2 == SENT || ug3 == SENT) {
                ug0 = ld_vol_u32(gt + jglob);
                ug1 = ld_vol_u32(gt + 256 + jglob);
                ug2 = ld_vol_u32(gt + 512 + jglob);
                ug3 = ld_vol_u32(gt + 768 + jglob);
            }
            const float* pf = (const float*)(psumU + (t & 1) * (32 * 65));
            int rqo = (jl >> 2);
            int off = ((jl >> 1) & 1) * 64 + ub * 2 + (jl & 1);
            float z[4] = {__uint_as_float(ug0), __uint_as_float(ug1),
                          __uint_as_float(ug2), __uint_as_float(ug3)};
#pragma unroll
            for (int q = 0; q < 4; q++) {
                const float* row = pf + (size_t)(q * 8 + rqo) * 130 + off;
                float sum = 0.f;
#pragma unroll
                for (int k8 = 0; k8 < 8; k8++) sum += row[k8 * 8];
                z[q] += sum;
            }
            dacc += dlt;
            float al = __fdividef(av, __logf(2.718281828459045f + dacc));
            float c = al * c0_reg + (1.f - al) * c_reg;
            c = sigm(z[1]) * c + sigm(z[0]) * tanh_fast(z[2]);
            c_reg = c;
            float h = sigm(z[3]) * tanh_fast(c);
            if (t < T_ - 1)
                st_vol(g_hT + (((size_t)t * NBG + g) * NSL + s) * 128 + jl * 4 + ub, h);
            out[(size_t)bg * (T_ * H_) + (size_t)t * H_ + jglob] = h;
        }
        // no second barrier: psum parity-buffered; h_s2 fragments warp-private
    }
}

// ---------------- launch ----------------
extern "C" void kernel_launch(void* const* d_in, const int* in_sizes, int n_in,
                              void* d_out, int out_size) {
    (void)in_sizes; (void)n_in; (void)out_size;
    const float* values = (const float*)d_in[0];
    const float* Deltas = (const float*)d_in[1];
    const float* W_att  = (const float*)d_in[2];
    const float* b_att  = (const float*)d_in[3];
    const float* W_ih   = (const float*)d_in[4];
    const float* W_hh   = (const float*)d_in[5];
    const float* b_ih   = (const float*)d_in[6];
    const float* b_hh   = (const float*)d_in[7];
    float* out = (float*)d_out;

    const size_t smem_scan = (size_t)(8 * 256 + 16384) * 4 + (size_t)2 * 32 * 65 * 8; // 107008 B
    const size_t smem_gemm_pad = 100 * 1024;  // UNUSED pad: caps gemm at 1 block/SM

    static cudaStream_t s2 = nullptr;
    static cudaEvent_t evP = nullptr, evM = nullptr, evG = nullptr;
    if (!s2) {   // first call = eager correctness run (not under capture)
        cudaStreamCreateWithFlags(&s2, cudaStreamNonBlocking);
        cudaEventCreateWithFlags(&evP, cudaEventDisableTiming);
        cudaEventCreateWithFlags(&evM, cudaEventDisableTiming);
        cudaEventCreateWithFlags(&evG, cudaEventDisableTiming);
        cudaFuncSetAttribute(k_scan, cudaFuncAttributeMaxDynamicSharedMemorySize,
                             (int)smem_scan);
        cudaFuncSetAttribute(k_gemm, cudaFuncAttributeMaxDynamicSharedMemorySize,
                             (int)smem_gemm_pad);
    }

    // fork poison to side stream (parallel with prepass)
    cudaEventRecord(evP, 0);               // fork point
    cudaStreamWaitEvent(s2, evP, 0);
    k_poison<<<(int)(N_POISON_U4 / 256), 256, 0, s2>>>();

    // prepass on capture stream
    k_wcbc<<<G4, D_>>>(W_ih, W_att, b_att, b_ih, b_hh);
    k_vlin0<<<dim3(B_, 4), 256>>>(values, W_att, b_att);
    k_a<<<(B_ * T_ * 32) / 256, 256>>>(values);
    cudaEventRecord(evM, 0);
    cudaStreamWaitEvent(s2, evM, 0);       // gemm needs poison (s2 order) + prepass

    // gemm on side stream: t-major grid (n fast, t slow) + occupancy pad (1 block/SM)
    k_gemm<<<dim3(G4 / 128, T_ / 2), 256, smem_gemm_pad, s2>>>(values);
    cudaEventRecord(evG, s2);

    // scan on capture stream: co-resides with gemm, consumes gates in t order
    k_scan<<<NB_SCAN, 256, smem_scan>>>(W_hh, Deltas, out);

    // join
    cudaStreamWaitEvent(0, evG, 0);
}

// round 17
// speedup vs baseline: 1.6217x; 1.6217x over previous
#include <cuda_runtime.h>
#include <math.h>
#include <stdint.h>

// Problem dims (fixed)
#define B_  64
#define T_  512
#define D_  256
#define H_  256
#define G4  1024          // 4*H
#define NBG 16            // batch groups (4 batches each)
#define NSL 8             // hidden-slice blocks per group (32 units each)
#define NB_SCAN (NBG*NSL) // 128 blocks
#define SENT 0x7FBFFFFFu  // NaN sentinel (unreachable from finite sigm*tanh)

typedef unsigned long long u64;
typedef unsigned int u32;

// ---------------- device scratch ----------------
__device__ float g_Wc[G4 * D_];                 // combined weight W_ih @ W_att
__device__ float g_bc[G4];                      // combined bias
__device__ float g_vlin0[B_ * D_];              // vlin[:,0]
__device__ float g_a[B_ * T_];                  // attention scalars a[b,t]
__device__ float g_gates[(size_t)T_ * B_ * G4]; // input gates [t][b][grow]
__device__ float g_hT[(size_t)T_ * NBG * NSL * 128]; // per-step h fragments [t][g][s][jl][b]

#define N_HT_U4  ((size_t)T_ * NBG * NSL * 128 / 4)       // 2097152 uint4

// ---------------- helpers ----------------
__device__ __forceinline__ float sigm(float x) {
    return __fdividef(1.0f, 1.0f + __expf(-x));
}
__device__ __forceinline__ float tanh_fast(float x) {
    return fmaf(2.0f, __fdividef(1.0f, 1.0f + __expf(-2.0f * x)), -1.0f);
}
__device__ __forceinline__ u64 pack2(float x, float y) {
    u64 r;
    asm("mov.b64 %0, {%1, %2};" : "=l"(r) : "f"(x), "f"(y));
    return r;
}
__device__ __forceinline__ u64 fma2(u64 a, u64 b, u64 c) {
    u64 d;
    asm("fma.rn.f32x2 %0, %1, %2, %3;" : "=l"(d) : "l"(a), "l"(b), "l"(c));
    return d;
}
__device__ __forceinline__ float2 unpack2(u64 v) {
    float2 f;
    asm("mov.b64 {%0, %1}, %2;" : "=f"(f.x), "=f"(f.y) : "l"(v));
    return f;
}
__device__ __forceinline__ uint4 ld_vol4(const float* p) {
    uint4 v;
    asm volatile("ld.volatile.global.v4.u32 {%0,%1,%2,%3}, [%4];"
                 : "=r"(v.x), "=r"(v.y), "=r"(v.z), "=r"(v.w) : "l"(p));
    return v;
}
__device__ __forceinline__ void st_vol(float* p, float v) {
    asm volatile("st.volatile.global.f32 [%0], %1;" :: "l"(p), "f"(v) : "memory");
}

// ---------------- kernel: poison per-step h buffers with sentinel ----------------
__global__ void k_poison() {
    size_t i = (size_t)blockIdx.x * blockDim.x + threadIdx.x;
    ((uint4*)g_hT)[i] = make_uint4(SENT, SENT, SENT, SENT);
}

// ---------------- kernel: Wc = W_ih @ W_att  AND  bc = W_ih@b_att + b_ih + b_hh ----
__global__ void k_wcbc(const float* __restrict__ W_ih, const float* __restrict__ W_att,
                       const float* __restrict__ b_att, const float* __restrict__ b_ih,
                       const float* __restrict__ b_hh) {
    int g = blockIdx.x;
    int k = threadIdx.x;
    __shared__ float wrow[D_];
    __shared__ float red[8];
    float w = W_ih[g * D_ + k];
    wrow[k] = w;
    __syncthreads();
    float pv = w * b_att[k];
#pragma unroll
    for (int off = 16; off; off >>= 1) pv += __shfl_down_sync(0xffffffffu, pv, off);
    if ((k & 31) == 0) red[k >> 5] = pv;
    float acc = 0.f;
#pragma unroll 8
    for (int d = 0; d < D_; d++) acc += wrow[d] * W_att[d * D_ + k];
    g_Wc[g * D_ + k] = acc;
    __syncthreads();
    if (k == 0) {
        float s = 0.f;
#pragma unroll
        for (int i = 0; i < 8; i++) s += red[i];
        g_bc[g] = s + b_ih[g] + b_hh[g];
    }
}

// ---------------- kernel: vlin0[b,:] = values[b,0,:] @ W_att^T + b_att ----------------
__global__ void k_vlin0(const float* __restrict__ values, const float* __restrict__ W_att,
                        const float* __restrict__ b_att) {
    int b = blockIdx.x;
    int wrp = threadIdx.x >> 5;
    int lane = threadIdx.x & 31;
    __shared__ float v[D_];
    v[threadIdx.x] = values[(size_t)b * T_ * D_ + threadIdx.x];
    __syncthreads();
    for (int i = 0; i < 8; i++) {
        int d = blockIdx.y * 64 + wrp * 8 + i;
        const float* wr = W_att + (size_t)d * D_;
        float acc = 0.f;
#pragma unroll
        for (int k = lane; k < D_; k += 32) acc += v[k] * wr[k];
#pragma unroll
        for (int off = 16; off; off >>= 1) acc += __shfl_down_sync(0xffffffffu, acc, off);
        if (lane == 0) g_vlin0[b * D_ + d] = acc + b_att[d];
    }
}

// ---------------- kernel: a[b,t] = sigmoid(vlin0[b] . values[b,t]) ----------------
__global__ void k_a(const float* __restrict__ values) {
    int w = (blockIdx.x * blockDim.x + threadIdx.x) >> 5;
    int lane = threadIdx.x & 31;
    int b = w >> 9, t = w & (T_ - 1);
    const float* vp = values + ((size_t)b * T_ + t) * D_;
    const float* lp = g_vlin0 + b * D_;
    float acc = 0.f;
#pragma unroll
    for (int k = lane; k < D_; k += 32) acc += vp[k] * lp[k];
#pragma unroll
    for (int off = 16; off; off >>= 1) acc += __shfl_down_sync(0xffffffffu, acc, off);
    if (lane == 0) g_a[w] = 1.0f / (1.0f + expf(-acc));
}

// ---------------- big GEMM: gates[t][b][g] = values[b,t,:].Wc[g,:] + bc[g] ----------
// Tile: (64 batch x 2 t) rows x 128 n per block, 256 threads, 8x8 microtile (FFMA2).
// Serial (before scan), 2 blocks/SM — the proven 400us configuration.
#define PA 132   // smem row pitch (floats), float4-aligned
__global__ __launch_bounds__(256) void k_gemm(const float* __restrict__ values) {
    int t0 = blockIdx.x * 2;
    int n0 = blockIdx.y * 128;

    __shared__ float As[16 * PA];   // [k][r]  r = tt*64 + b
    __shared__ float Bs[16 * PA];   // [k][n]

    int tid = threadIdx.x;
    int tx = tid & 15;              // row quad group
    int ty = tid >> 4;              // n quad group

    const float* gp;
    float* scol;
    {
        int r = tid & 127;
        if (tid < 128) {
            int b = r & 63, tt = r >> 6;
            gp = values + ((size_t)b * T_ + t0 + tt) * D_;
            scol = As + r;
        } else {
            gp = g_Wc + (size_t)(n0 + r) * D_;
            scol = Bs + r;
        }
    }

    float4 pf0 = ((const float4*)gp)[0];
    float4 pf1 = ((const float4*)gp)[1];
    float4 pf2 = ((const float4*)gp)[2];
    float4 pf3 = ((const float4*)gp)[3];

    u64 acc[2][4][4];
#pragma unroll
    for (int a = 0; a < 2; a++)
#pragma unroll
        for (int i = 0; i < 4; i++)
#pragma unroll
            for (int j = 0; j < 4; j++) acc[a][i][j] = 0ull;

    for (int c = 0; c < 16; c++) {
        __syncthreads();
        scol[ 0 * PA] = pf0.x; scol[ 1 * PA] = pf0.y; scol[ 2 * PA] = pf0.z; scol[ 3 * PA] = pf0.w;
        scol[ 4 * PA] = pf1.x; scol[ 5 * PA] = pf1.y; scol[ 6 * PA] = pf1.z; scol[ 7 * PA] = pf1.w;
        scol[ 8 * PA] = pf2.x; scol[ 9 * PA] = pf2.y; scol[10 * PA] = pf2.z; scol[11 * PA] = pf2.w;
        scol[12 * PA] = pf3.x; scol[13 * PA] = pf3.y; scol[14 * PA] = pf3.z; scol[15 * PA] = pf3.w;
        __syncthreads();

        if (c < 15) {
            const float* np = gp + (c + 1) * 16;
            pf0 = ((const float4*)np)[0];
            pf1 = ((const float4*)np)[1];
            pf2 = ((const float4*)np)[2];
            pf3 = ((const float4*)np)[3];
        }

#pragma unroll
        for (int k = 0; k < 16; k++) {
            float4 a0 = *(const float4*)&As[k * PA + 4 * tx];
            float4 a1 = *(const float4*)&As[k * PA + 64 + 4 * tx];
            float4 bv0 = *(const float4*)&Bs[k * PA + 4 * ty];
            float4 bv1 = *(const float4*)&Bs[k * PA + 64 + 4 * ty];
            u64 b00 = *(u64*)&bv0.x;
            u64 b01 = *(u64*)&bv0.z;
            u64 b10 = *(u64*)&bv1.x;
            u64 b11 = *(u64*)&bv1.z;

            u64 p;
            p = pack2(a0.x, a0.x);
            acc[0][0][0] = fma2(p, b00, acc[0][0][0]); acc[0][0][1] = fma2(p, b01, acc[0][0][1]);
            acc[0][0][2] = fma2(p, b10, acc[0][0][2]); acc[0][0][3] = fma2(p, b11, acc[0][0][3]);
            p = pack2(a0.y, a0.y);
            acc[0][1][0] = fma2(p, b00, acc[0][1][0]); acc[0][1][1] = fma2(p, b01, acc[0][1][1]);
            acc[0][1][2] = fma2(p, b10, acc[0][1][2]); acc[0][1][3] = fma2(p, b11, acc[0][1][3]);
            p = pack2(a0.z, a0.z);
            acc[0][2][0] = fma2(p, b00, acc[0][2][0]); acc[0][2][1] = fma2(p, b01, acc[0][2][1]);
            acc[0][2][2] = fma2(p, b10, acc[0][2][2]); acc[0][2][3] = fma2(p, b11, acc[0][2][3]);
            p = pack2(a0.w, a0.w);
            acc[0][3][0] = fma2(p, b00, acc[0][3][0]); acc[0][3][1] = fma2(p, b01, acc[0][3][1]);
            acc[0][3][2] = fma2(p, b10, acc[0][3][2]); acc[0][3][3] = fma2(p, b11, acc[0][3][3]);
            p = pack2(a1.x, a1.x);
            acc[1][0][0] = fma2(p, b00, acc[1][0][0]); acc[1][0][1] = fma2(p, b01, acc[1][0][1]);
            acc[1][0][2] = fma2(p, b10, acc[1][0][2]); acc[1][0][3] = fma2(p, b11, acc[1][0][3]);
            p = pack2(a1.y, a1.y);
            acc[1][1][0] = fma2(p, b00, acc[1][1][0]); acc[1][1][1] = fma2(p, b01, acc[1][1][1]);
            acc[1][1][2] = fma2(p, b10, acc[1][1][2]); acc[1][1][3] = fma2(p, b11, acc[1][1][3]);
            p = pack2(a1.z, a1.z);
            acc[1][2][0] = fma2(p, b00, acc[1][2][0]); acc[1][2][1] = fma2(p, b01, acc[1][2][1]);
            acc[1][2][2] = fma2(p, b10, acc[1][2][2]); acc[1][2][3] = fma2(p, b11, acc[1][2][3]);
            p = pack2(a1.w, a1.w);
            acc[1][3][0] = fma2(p, b00, acc[1][3][0]); acc[1][3][1] = fma2(p, b01, acc[1][3][1]);
            acc[1][3][2] = fma2(p, b10, acc[1][3][2]); acc[1][3][3] = fma2(p, b11, acc[1][3][3]);
        }
    }

    float4 biasA = *(const float4*)&g_bc[n0 + 4 * ty];
    float4 biasB = *(const float4*)&g_bc[n0 + 64 + 4 * ty];
#pragma unroll
    for (int tt = 0; tt < 2; tt++) {
#pragma unroll
        for (int i = 0; i < 4; i++) {
            int b = 4 * tx + i;
            float* op = g_gates + ((size_t)(t0 + tt) * B_ + b) * G4 + n0;
            float2 p0 = unpack2(acc[tt][i][0]);
            float2 p1 = unpack2(acc[tt][i][1]);
            float2 p2 = unpack2(acc[tt][i][2]);
            float2 p3 = unpack2(acc[tt][i][3]);
            *(float4*)&op[4 * ty] =
                make_float4(p0.x + biasA.x, p0.y + biasA.y, p1.x + biasA.z, p1.y + biasA.w);
            *(float4*)&op[64 + 4 * ty] =
                make_float4(p2.x + biasB.x, p2.y + biasB.y, p3.x + biasB.z, p3.y + biasB.w);
        }
    }
}

// ---------------- persistent scan kernel (L2 data-as-tag, serial after gemm) ------
// 128 blocks = 16 groups x 8 slices. Block (g,s): batches 4g..4g+3, units 32s..32s+31.
// W slice FULLY in registers (wA+wB, 128 regs — no co-residency constraint).
// h exchange: per-step sentinel-poisoned L2 buffers, consumer polls the data itself
// (proven R12). gates/Deltas/a via plain loads (gemm completed). alpha in-loop.
// Single __syncthreads per step (parity-buffered psum, proven R13+).
__global__ __launch_bounds__(256, 1) void k_scan(const float* __restrict__ Whh,
                                                 const float* __restrict__ Deltas,
                                                 float* __restrict__ out) {
    __shared__ float h_s2[NSL * 256];          // [ks][b][jl dup-pairs]  8KB
    __shared__ u64  psumU[2 * 32 * 65];        // parity x [rq][(rp*8+ks)*4 + b]

    int tid = threadIdx.x;
    int bid = blockIdx.x;
    int g = bid >> 3, s = bid & 7;

    int ks = tid >> 5;            // warp id == peer slice consumed
    int rq = tid & 31;            // row quad (rows 4rq..4rq+3)

    // ---- load W slice into registers, pre-packed as row-pairs ----
    u64 wA[32], wB[32];
    {
        int r0 = 4 * rq;
        int q = r0 >> 5;
        int jb = r0 & 31;
        const float* wb = Whh + (size_t)(q * 256 + s * 32 + jb) * 256 + 32 * ks;
#pragma unroll
        for (int kc = 0; kc < 32; kc++) {
            wA[kc] = pack2(wb[kc], wb[256 + kc]);
            wB[kc] = pack2(wb[512 + kc], wb[768 + kc]);
        }
    }

    // update identity (tid < 128)
    int ub = tid >> 5;            // 0..3 batch-local
    int jl = tid & 31;
    int bg = g * 4 + ub;          // global batch
    int jglob = s * 32 + jl;      // global hidden unit

    float c_reg = 0.f, c0_reg = 0.f, dacc = 0.f;

    // ---- prologue t = 0 (h=0, c=0; carry c stays zero — faithful quirk) ----
    if (tid < 128) {
        const float* g0 = g_gates + (size_t)bg * G4;
        float zi = g0[0 * H_ + jglob];
        float zg = g0[2 * H_ + jglob];
        float zo = g0[3 * H_ + jglob];
        c0_reg = sigm(zi) * tanh_fast(zg);
        float h1 = sigm(zo) * tanh_fast(c0_reg);
        dacc = Deltas[(size_t)bg * T_ * D_ + jglob];   // cumsum through t=0
        st_vol(g_hT + (((size_t)0 * NBG + g) * NSL + s) * 128 + jl * 4 + ub, h1);
        out[(size_t)bg * (T_ * H_) + jglob] = h1;
    }

    for (int t = 1; t < T_; t++) {
        // prefetch gates/Deltas/a (plain loads; independent of the h poll)
        float gin0 = 0.f, gin1 = 0.f, gin2 = 0.f, gin3 = 0.f, dlt = 0.f, av = 0.f;
        if (tid < 128) {
            const float* gt = g_gates + ((size_t)t * B_ + bg) * G4;
            gin0 = gt[0 * H_ + jglob];
            gin1 = gt[1 * H_ + jglob];
            gin2 = gt[2 * H_ + jglob];
            gin3 = gt[3 * H_ + jglob];
            dlt  = Deltas[((size_t)bg * T_ + t) * D_ + jglob];
            av   = g_a[bg * T_ + t];
        }

        // poll peer h fragment: data IS the tag (sentinel = not yet written)
        {
            const float* fp = g_hT + (((size_t)(t - 1) * NBG + g) * NSL + ks) * 128 + rq * 4;
            uint4 u;
            do {
                u = ld_vol4(fp);
            } while (u.x == SENT || u.y == SENT || u.z == SENT || u.w == SENT);
            float2* d = (float2*)(h_s2 + ks * 256);
            float hx = __uint_as_float(u.x);
            float hy = __uint_as_float(u.y);
            float hz = __uint_as_float(u.z);
            float hw = __uint_as_float(u.w);
            d[0 * 32 + rq] = make_float2(hx, hx);
            d[1 * 32 + rq] = make_float2(hy, hy);
            d[2 * 32 + rq] = make_float2(hz, hz);
            d[3 * 32 + rq] = make_float2(hw, hw);
        }
        __syncwarp();

        // dot: W in regs, h via broadcast LDS.128 dup-pairs, pure FFMA2
        {
            const float* hp = h_s2 + ks * 256;
            u64 a00 = 0, a01 = 0, a02 = 0, a03 = 0;
            u64 a10 = 0, a11 = 0, a12 = 0, a13 = 0;
#pragma unroll
            for (int m = 0; m < 16; m++) {
                float4 q0 = *(const float4*)(hp + 4 * m);
                float4 q1 = *(const float4*)(hp + 64 + 4 * m);
                float4 q2 = *(const float4*)(hp + 128 + 4 * m);
                float4 q3 = *(const float4*)(hp + 192 + 4 * m);
                u64 wa0 = wA[2 * m], wa1 = wA[2 * m + 1];
                u64 wb0 = wB[2 * m], wb1 = wB[2 * m + 1];
                u64 h00 = *(u64*)&q0.x, h01 = *(u64*)&q0.z;
                u64 h10 = *(u64*)&q1.x, h11 = *(u64*)&q1.z;
                u64 h20 = *(u64*)&q2.x, h21 = *(u64*)&q2.z;
                u64 h30 = *(u64*)&q3.x, h31 = *(u64*)&q3.z;
                a00 = fma2(wa0, h00, a00); a00 = fma2(wa1, h01, a00);
                a01 = fma2(wa0, h10, a01); a01 = fma2(wa1, h11, a01);
                a02 = fma2(wa0, h20, a02); a02 = fma2(wa1, h21, a02);
                a03 = fma2(wa0, h30, a03); a03 = fma2(wa1, h31, a03);
                a10 = fma2(wb0, h00, a10); a10 = fma2(wb1, h01, a10);
                a11 = fma2(wb0, h10, a11); a11 = fma2(wb1, h11, a11);
                a12 = fma2(wb0, h20, a12); a12 = fma2(wb1, h21, a12);
                a13 = fma2(wb0, h30, a13); a13 = fma2(wb1, h31, a13);
            }
            u64* pb = psumU + (t & 1) * (32 * 65) + rq * 65 + ks * 4;
            pb[0] = a00; pb[1] = a01; pb[2] = a02; pb[3] = a03;
            pb[32 + 0] = a10; pb[32 + 1] = a11; pb[32 + 2] = a12; pb[32 + 3] = a13;
        }
        __syncthreads();   // psum[t&1] ready (single barrier per step)

        // cell update: 128 threads, one per (batch, unit)
        if (tid < 128) {
            const float* pf = (const float*)(psumU + (t & 1) * (32 * 65));
            int rqo = (jl >> 2);
            int off = ((jl >> 1) & 1) * 64 + ub * 2 + (jl & 1);
            float z[4] = {gin0, gin1, gin2, gin3};
#pragma unroll
            for (int q = 0; q < 4; q++) {
                const float* row = pf + (size_t)(q * 8 + rqo) * 130 + off;
                float sum = 0.f;
#pragma unroll
                for (int k8 = 0; k8 < 8; k8++) sum += row[k8 * 8];
                z[q] += sum;
            }
            dacc += dlt;
            float al = __fdividef(av, __logf(2.718281828459045f + dacc));
            float c = al * c0_reg + (1.f - al) * c_reg;
            c = sigm(z[1]) * c + sigm(z[0]) * tanh_fast(z[2]);
            c_reg = c;
            float h = sigm(z[3]) * tanh_fast(c);
            if (t < T_ - 1)
                st_vol(g_hT + (((size_t)t * NBG + g) * NSL + s) * 128 + jl * 4 + ub, h);
            out[(size_t)bg * (T_ * H_) + (size_t)t * H_ + jglob] = h;
        }
        // no second barrier: psum parity-buffered; h_s2 fragments warp-private
    }
}

// ---------------- launch ----------------
extern "C" void kernel_launch(void* const* d_in, const int* in_sizes, int n_in,
                              void* d_out, int out_size) {
    (void)in_sizes; (void)n_in; (void)out_size;
    const float* values = (const float*)d_in[0];
    const float* Deltas = (const float*)d_in[1];
    const float* W_att  = (const float*)d_in[2];
    const float* b_att  = (const float*)d_in[3];
    const float* W_ih   = (const float*)d_in[4];
    const float* W_hh   = (const float*)d_in[5];
    const float* b_ih   = (const float*)d_in[6];
    const float* b_hh   = (const float*)d_in[7];
    float* out = (float*)d_out;

    static cudaStream_t s2 = nullptr;
    static cudaEvent_t evF = nullptr, evP = nullptr;
    if (!s2) {   // first call = eager correctness run (not under capture)
        cudaStreamCreateWithFlags(&s2, cudaStreamNonBlocking);
        cudaEventCreateWithFlags(&evF, cudaEventDisableTiming);
        cudaEventCreateWithFlags(&evP, cudaEventDisableTiming);
    }

    // poison h ring on side stream, overlapped with the prepass + gemm
    cudaEventRecord(evF, 0);
    cudaStreamWaitEvent(s2, evF, 0);
    k_poison<<<(int)(N_HT_U4 / 256), 256, 0, s2>>>();
    cudaEventRecord(evP, s2);

    // prepass + gemm on the main stream (serial; gemm = proven 400us config)
    k_wcbc<<<G4, D_>>>(W_ih, W_att, b_att, b_ih, b_hh);
    k_vlin0<<<dim3(B_, 4), 256>>>(values, W_att, b_att);
    k_a<<<(B_ * T_ * 32) / 256, 256>>>(values);
    k_gemm<<<dim3(T_ / 2, G4 / 128), 256>>>(values);

    // scan needs the poison done
    cudaStreamWaitEvent(0, evP, 0);
    k_scan<<<NB_SCAN, 256>>>(W_hh, Deltas, out);
}